// round 1
// baseline (speedup 1.0000x reference)
#include <cuda_runtime.h>
#include <cstdint>

#define N_NODES  20000
#define N_EDGES  160000
#define N_GRAPHS 100

// ---------------- scratch (device globals; no allocation allowed) ----------------
__device__ float    g_bufA[N_NODES * 1024];   // xl of current layer
__device__ float    g_bufB[N_NODES * 1024];   // xr of current layer
__device__ float    g_bufC[N_NODES * 1024];   // layer1 out / layer3 out
__device__ float    g_bufD[N_NODES * 1024];   // layer2 out
__device__ float    g_logit[N_EDGES * 6];     // logits -> exp values
__device__ unsigned g_mx[N_NODES * 6];        // encoded segment max
__device__ float    g_den[N_NODES * 6];       // softmax denominators
__device__ int      g_last[N_GRAPHS];         // master node indices

// monotone float<->uint encoding for atomicMax on floats (any sign)
__device__ __forceinline__ unsigned enc(float f) {
    unsigned u = __float_as_uint(f);
    return (u & 0x80000000u) ? ~u : (u | 0x80000000u);
}
__device__ __forceinline__ float dec(unsigned u) {
    return (u & 0x80000000u) ? __uint_as_float(u ^ 0x80000000u) : __uint_as_float(~u);
}

// ---------------- generic tiled fp32 GEMM: C[M,N] = A[M,K] @ B[K,N] ----------------
template <int BM, int BN, int BK, int TM, int TN>
__global__ void gemm_kernel(const float* __restrict__ A, const float* __restrict__ B,
                            float* __restrict__ C, int M, int N, int K) {
    __shared__ float As[BK][BM];
    __shared__ float Bs[BK][BN];
    const int bm = blockIdx.y * BM;
    const int bn = blockIdx.x * BN;
    const int tid = threadIdx.x;                 // 256 threads
    const int tx = tid % (BN / TN);              // 16
    const int ty = tid / (BN / TN);              // 16

    float acc[TM][TN];
#pragma unroll
    for (int i = 0; i < TM; i++)
#pragma unroll
        for (int j = 0; j < TN; j++) acc[i][j] = 0.f;

    for (int k0 = 0; k0 < K; k0 += BK) {
        // load A tile (BM x BK) transposed into As[BK][BM]
#pragma unroll
        for (int i = tid; i < BM * BK; i += 256) {
            int r = i / BK, c = i % BK;
            float v = 0.f;
            if (bm + r < M) v = A[(size_t)(bm + r) * K + k0 + c];
            As[c][r] = v;
        }
        // load B tile (BK x BN)
#pragma unroll
        for (int i = tid; i < BK * BN; i += 256) {
            int r = i / BN, c = i % BN;
            Bs[r][c] = B[(size_t)(k0 + r) * N + bn + c];
        }
        __syncthreads();
#pragma unroll
        for (int kk = 0; kk < BK; kk++) {
            float4 av = *reinterpret_cast<const float4*>(&As[kk][ty * TM]);
            float4 bv = *reinterpret_cast<const float4*>(&Bs[kk][tx * TN]);
            float a[TM] = {av.x, av.y, av.z, av.w};
            float b[TN] = {bv.x, bv.y, bv.z, bv.w};
#pragma unroll
            for (int i = 0; i < TM; i++)
#pragma unroll
                for (int j = 0; j < TN; j++) acc[i][j] += a[i] * b[j];
        }
        __syncthreads();
    }
#pragma unroll
    for (int i = 0; i < TM; i++) {
        int r = bm + ty * TM + i;
        if (r < M) {
#pragma unroll
            for (int j = 0; j < TN; j++)
                C[(size_t)r * N + bn + tx * TN + j] = acc[i][j];
        }
    }
}

// ---------------- edge logit + fused segment-max ----------------
// warp-per-edge; 8 warps/block, 8 edges per warp -> 64 edges/block.
// logit[e,h] = sum_c att[h,c] * leaky_relu(xl[src][h,c] + xr[dst][h,c] + (ea[e]@We)[h,c])
template <int H, int C, bool EA>
__global__ void edge_logit_kernel(const float* __restrict__ xl, const float* __restrict__ xr,
                                  const float* __restrict__ ea, const float* __restrict__ We,
                                  const float* __restrict__ att,
                                  const int* __restrict__ src, const int* __restrict__ dst,
                                  float* __restrict__ logit, unsigned* __restrict__ mx, int E) {
    constexpr int HC = H * C;
    __shared__ float s_att[HC];
    __shared__ float s_We[EA ? 8 * HC : 1];
    for (int i = threadIdx.x; i < HC; i += blockDim.x) s_att[i] = att[i];
    if (EA)
        for (int i = threadIdx.x; i < 8 * HC; i += blockDim.x) s_We[i] = We[i];
    __syncthreads();

    const int warp = threadIdx.x >> 5, lane = threadIdx.x & 31;
    const int base = (blockIdx.x * 8 + warp) * 8;
    for (int i = 0; i < 8; i++) {
        const int e = base + i;
        if (e >= E) return;
        const int s = src[e], d = dst[e];
        float ear[8];
        if (EA) {
#pragma unroll
            for (int k = 0; k < 8; k++) ear[k] = __ldg(&ea[(size_t)e * 8 + k]);
        }
        const float* xls = xl + (size_t)s * HC;
        const float* xrd = xr + (size_t)d * HC;
#pragma unroll
        for (int h = 0; h < H; h++) {
            float acc = 0.f;
            for (int c = lane; c < C; c += 32) {
                float v = xls[h * C + c] + xrd[h * C + c];
                if (EA) {
#pragma unroll
                    for (int k = 0; k < 8; k++) v += ear[k] * s_We[k * HC + h * C + c];
                }
                v = (v >= 0.f) ? v : 0.2f * v;
                acc += s_att[h * C + c] * v;
            }
#pragma unroll
            for (int o = 16; o > 0; o >>= 1) acc += __shfl_xor_sync(0xffffffffu, acc, o);
            if (lane == 0) {
                logit[(size_t)e * H + h] = acc;
                atomicMax(&mx[d * H + h], enc(acc));
            }
        }
    }
}

// ---------------- exp(logit - max) + segment-sum denominator ----------------
template <int H>
__global__ void edge_exp_kernel(float* __restrict__ logit, const unsigned* __restrict__ mx,
                                float* __restrict__ den, const int* __restrict__ dst, int E) {
    int i = blockIdx.x * blockDim.x + threadIdx.x;
    if (i >= E * H) return;
    int e = i / H, h = i - e * H;
    int d = dst[e];
    float m = dec(mx[d * H + h]);
    float ex = __expf(logit[i] - m);
    logit[i] = ex;
    atomicAdd(&den[d * H + h], ex);
}

// ---------------- alpha-weighted aggregation (scatter-add) ----------------
template <int H, int C>
__global__ void edge_aggr_kernel(const float* __restrict__ xl, const float* __restrict__ ex,
                                 const float* __restrict__ den,
                                 const int* __restrict__ src, const int* __restrict__ dst,
                                 float* __restrict__ out, int E) {
    constexpr int HC = H * C;
    const int warp = threadIdx.x >> 5, lane = threadIdx.x & 31;
    const int e = blockIdx.x * 8 + warp;
    if (e >= E) return;
    const int s = src[e], d = dst[e];
    const float* xls = xl + (size_t)s * HC;
    float* outd = out + (size_t)d * HC;
#pragma unroll
    for (int h = 0; h < H; h++) {
        float alpha = ex[(size_t)e * H + h] / (den[d * H + h] + 1e-16f);
        for (int c = lane; c < C; c += 32)
            atomicAdd(&outd[h * C + c], alpha * xls[h * C + c]);
    }
}

// ---------------- small helpers ----------------
__global__ void fill_u32_kernel(unsigned* p, unsigned v, int n) {
    int i = blockIdx.x * blockDim.x + threadIdx.x;
    if (i < n) p[i] = v;
}
__global__ void fill_f32_kernel(float* p, float v, int n) {
    int i = blockIdx.x * blockDim.x + threadIdx.x;
    if (i < n) p[i] = v;
}
__global__ void init_bias_kernel(float* __restrict__ out, const float* __restrict__ b, int n, int D) {
    int i = blockIdx.x * blockDim.x + threadIdx.x;
    if (i < n) out[i] = b[i % D];
}
__global__ void relu_kernel(float* p, int n) {
    int i = blockIdx.x * blockDim.x + threadIdx.x;
    if (i < n) p[i] = fmaxf(p[i], 0.f);
}
__global__ void last_idx_kernel(const int* __restrict__ n_nodes, int* __restrict__ last, int G) {
    if (threadIdx.x == 0 && blockIdx.x == 0) {
        int s = 0;
        for (int i = 0; i < G; i++) { s += n_nodes[i]; last[i] = s - 1; }
    }
}

// ---------------- final MLP head: out[g] = relu(h[last[g]] @ W1 + b1) @ W2 + b2 ----------------
__global__ void fc_kernel(const float* __restrict__ h, const int* __restrict__ last,
                          const float* __restrict__ W1, const float* __restrict__ b1,
                          const float* __restrict__ W2, const float* __restrict__ b2,
                          float* __restrict__ out) {
    __shared__ float row[384];
    __shared__ float red[64];
    const int g = blockIdx.x, t = threadIdx.x;   // 64 threads
    const int node = last[g];
    for (int i = t; i < 384; i += 64) row[i] = h[(size_t)node * 384 + i];
    __syncthreads();
    float acc = b1[t];
    for (int k = 0; k < 384; k++) acc += row[k] * W1[k * 64 + t];
    acc = fmaxf(acc, 0.f);
    red[t] = acc * W2[t];
    __syncthreads();
    if (t < 32) {
        float p = red[t] + red[t + 32];
#pragma unroll
        for (int o = 16; o > 0; o >>= 1) p += __shfl_xor_sync(0xffffffffu, p, o);
        if (t == 0) out[g] = p + b2[0];
    }
}

// ---------------- launch ----------------
extern "C" void kernel_launch(void* const* d_in, const int* in_sizes, int n_in,
                              void* d_out, int out_size) {
    const float* x       = (const float*)d_in[0];
    const float* ea      = (const float*)d_in[1];
    const float* Wl1     = (const float*)d_in[2];
    const float* Wr1     = (const float*)d_in[3];
    const float* We1     = (const float*)d_in[4];
    const float* att1    = (const float*)d_in[5];
    const float* b1      = (const float*)d_in[6];
    const float* Wl2     = (const float*)d_in[7];
    const float* Wr2     = (const float*)d_in[8];
    const float* We2     = (const float*)d_in[9];
    const float* att2    = (const float*)d_in[10];
    const float* b2      = (const float*)d_in[11];
    const float* Wlp     = (const float*)d_in[12];
    const float* Wrp     = (const float*)d_in[13];
    const float* attp    = (const float*)d_in[14];
    const float* bp      = (const float*)d_in[15];
    const float* Wfc1    = (const float*)d_in[16];
    const float* bfc1    = (const float*)d_in[17];
    const float* Wfc2    = (const float*)d_in[18];
    const float* bfc2    = (const float*)d_in[19];
    const int*   ei      = (const int*)d_in[20];
    const int*   eim     = (const int*)d_in[21];
    const int*   n_nodes = (const int*)d_in[22];

    const int N = N_NODES, E = N_EDGES;
    const int* src  = ei;
    const int* dst  = ei + E;
    const int* srcm = eim;
    const int* dstm = eim + E;

    float *bufA, *bufB, *bufC, *bufD, *logit, *den;
    unsigned* mx;
    int* last;
    cudaGetSymbolAddress((void**)&bufA, g_bufA);
    cudaGetSymbolAddress((void**)&bufB, g_bufB);
    cudaGetSymbolAddress((void**)&bufC, g_bufC);
    cudaGetSymbolAddress((void**)&bufD, g_bufD);
    cudaGetSymbolAddress((void**)&logit, g_logit);
    cudaGetSymbolAddress((void**)&mx, g_mx);
    cudaGetSymbolAddress((void**)&den, g_den);
    cudaGetSymbolAddress((void**)&last, g_last);

    const int MB = (N + 63) / 64;   // 313 row-blocks

    // ===== Layer 1: GATv2(64 -> 4x256), edge_attr =====
    gemm_kernel<64, 64, 16, 4, 4><<<dim3(1024 / 64, MB), 256>>>(x, Wl1, bufA, N, 1024, 64);
    gemm_kernel<64, 64, 16, 4, 4><<<dim3(1024 / 64, MB), 256>>>(x, Wr1, bufB, N, 1024, 64);
    fill_u32_kernel<<<(N * 4 + 255) / 256, 256>>>(mx, 0u, N * 4);
    fill_f32_kernel<<<(N * 4 + 255) / 256, 256>>>(den, 0.f, N * 4);
    edge_logit_kernel<4, 256, true><<<(E + 63) / 64, 256>>>(bufA, bufB, ea, We1, att1,
                                                            src, dst, logit, mx, E);
    edge_exp_kernel<4><<<(E * 4 + 255) / 256, 256>>>(logit, mx, den, dst, E);
    init_bias_kernel<<<(N * 1024 + 255) / 256, 256>>>(bufC, b1, N * 1024, 1024);
    edge_aggr_kernel<4, 256><<<(E + 7) / 8, 256>>>(bufA, logit, den, src, dst, bufC, E);
    relu_kernel<<<(N * 1024 + 255) / 256, 256>>>(bufC, N * 1024);

    // ===== Layer 2: GATv2(1024 -> 4x64), edge_attr =====
    gemm_kernel<64, 64, 16, 4, 4><<<dim3(256 / 64, MB), 256>>>(bufC, Wl2, bufA, N, 256, 1024);
    gemm_kernel<64, 64, 16, 4, 4><<<dim3(256 / 64, MB), 256>>>(bufC, Wr2, bufB, N, 256, 1024);
    fill_u32_kernel<<<(N * 4 + 255) / 256, 256>>>(mx, 0u, N * 4);
    fill_f32_kernel<<<(N * 4 + 255) / 256, 256>>>(den, 0.f, N * 4);
    edge_logit_kernel<4, 64, true><<<(E + 63) / 64, 256>>>(bufA, bufB, ea, We2, att2,
                                                           src, dst, logit, mx, E);
    edge_exp_kernel<4><<<(E * 4 + 255) / 256, 256>>>(logit, mx, den, dst, E);
    init_bias_kernel<<<(N * 256 + 255) / 256, 256>>>(bufD, b2, N * 256, 256);
    edge_aggr_kernel<4, 64><<<(E + 7) / 8, 256>>>(bufA, logit, den, src, dst, bufD, E);
    relu_kernel<<<(N * 256 + 255) / 256, 256>>>(bufD, N * 256);

    // ===== Layer 3: GATv2(256 -> 6x64), no edge_attr, master edge index =====
    gemm_kernel<64, 64, 16, 4, 4><<<dim3(384 / 64, MB), 256>>>(bufD, Wlp, bufA, N, 384, 256);
    gemm_kernel<64, 64, 16, 4, 4><<<dim3(384 / 64, MB), 256>>>(bufD, Wrp, bufB, N, 384, 256);
    fill_u32_kernel<<<(N * 6 + 255) / 256, 256>>>(mx, 0u, N * 6);
    fill_f32_kernel<<<(N * 6 + 255) / 256, 256>>>(den, 0.f, N * 6);
    edge_logit_kernel<6, 64, false><<<(E + 63) / 64, 256>>>(bufA, bufB, nullptr, nullptr, attp,
                                                            srcm, dstm, logit, mx, E);
    edge_exp_kernel<6><<<(E * 6 + 255) / 256, 256>>>(logit, mx, den, dstm, E);
    init_bias_kernel<<<(N * 384 + 255) / 256, 256>>>(bufC, bp, N * 384, 384);
    edge_aggr_kernel<6, 64><<<(E + 7) / 8, 256>>>(bufA, logit, den, srcm, dstm, bufC, E);

    // ===== readout + MLP head =====
    last_idx_kernel<<<1, 32>>>(n_nodes, last, N_GRAPHS);
    fc_kernel<<<N_GRAPHS, 64>>>(bufC, last, Wfc1, bfc1, Wfc2, bfc2, (float*)d_out);
}

// round 2
// speedup vs baseline: 1.3485x; 1.3485x over previous
#include <cuda_runtime.h>
#include <cstdint>

#define N_NODES  20000
#define N_EDGES  160000
#define N_GRAPHS 100

// ---------------- scratch (device globals; no allocation allowed) ----------------
__device__ float    g_bufA[N_NODES * 1024];   // xl of current layer
__device__ float    g_bufB[N_NODES * 1024];   // xr of current layer
__device__ float    g_bufC[N_NODES * 1024];   // layer1 out / layer3 out
__device__ float    g_bufD[N_NODES * 1024];   // layer2 out
__device__ float    g_logit[N_EDGES * 6];     // logits -> exp values
__device__ unsigned g_mx[N_NODES * 6];        // encoded segment max
__device__ float    g_den[N_NODES * 6];       // softmax denominators
__device__ int      g_last[N_GRAPHS];         // master node indices

// monotone float<->uint encoding for atomicMax on floats (any sign)
__device__ __forceinline__ unsigned enc(float f) {
    unsigned u = __float_as_uint(f);
    return (u & 0x80000000u) ? ~u : (u | 0x80000000u);
}
__device__ __forceinline__ float dec(unsigned u) {
    return (u & 0x80000000u) ? __uint_as_float(u ^ 0x80000000u) : __uint_as_float(~u);
}

// ---------------- tiled fp32 GEMM: C[M,N] = A[M,K] @ B[K,N] ----------------
// BM=128, BN=128, BK=16, 256 threads, TM=8, TN=8. RELU applies relu to A on load.
template <bool RELU>
__global__ void __launch_bounds__(256, 2)
gemm128_kernel(const float* __restrict__ A, const float* __restrict__ B,
               float* __restrict__ C, int M, int N, int K) {
    constexpr int BM = 128, BN = 128, BK = 16, TM = 8, TN = 8;
    __shared__ float As[BK][BM];
    __shared__ float Bs[BK][BN];
    const int bm = blockIdx.y * BM;
    const int bn = blockIdx.x * BN;
    const int tid = threadIdx.x;
    const int tx = tid & 15;        // 0..15
    const int ty = tid >> 4;        // 0..15

    float acc[TM][TN];
#pragma unroll
    for (int i = 0; i < TM; i++)
#pragma unroll
        for (int j = 0; j < TN; j++) acc[i][j] = 0.f;

    // A-load indices: 512 float4s per tile, 2 per thread
    const int ar0 = tid >> 1;              // rows 0..127 (first half)
    const int ak0 = (tid & 1) * 4;         // k offset 0 or 4... need full BK=16
    // Actually: BM*BK/4 = 512 float4; thread v handles v and v+256.
    for (int k0 = 0; k0 < K; k0 += BK) {
        // ---- load A tile (BM x BK) transposed into As[BK][BM] ----
#pragma unroll
        for (int v = tid; v < BM * BK / 4; v += 256) {
            int row = v >> 2;               // BK/4 = 4 float4 per row
            int kq = (v & 3) * 4;
            float4 t = make_float4(0.f, 0.f, 0.f, 0.f);
            if (bm + row < M)
                t = *reinterpret_cast<const float4*>(&A[(size_t)(bm + row) * K + k0 + kq]);
            if (RELU) {
                t.x = fmaxf(t.x, 0.f); t.y = fmaxf(t.y, 0.f);
                t.z = fmaxf(t.z, 0.f); t.w = fmaxf(t.w, 0.f);
            }
            As[kq + 0][row] = t.x;
            As[kq + 1][row] = t.y;
            As[kq + 2][row] = t.z;
            As[kq + 3][row] = t.w;
        }
        // ---- load B tile (BK x BN) ----
#pragma unroll
        for (int v = tid; v < BK * BN / 4; v += 256) {
            int row = v >> 5;               // BN/4 = 32 float4 per row
            int cq = (v & 31) * 4;
            *reinterpret_cast<float4*>(&Bs[row][cq]) =
                *reinterpret_cast<const float4*>(&B[(size_t)(k0 + row) * N + bn + cq]);
        }
        __syncthreads();
#pragma unroll
        for (int kk = 0; kk < BK; kk++) {
            float4 a0 = *reinterpret_cast<const float4*>(&As[kk][ty * TM]);
            float4 a1 = *reinterpret_cast<const float4*>(&As[kk][ty * TM + 4]);
            float4 b0 = *reinterpret_cast<const float4*>(&Bs[kk][tx * TN]);
            float4 b1 = *reinterpret_cast<const float4*>(&Bs[kk][tx * TN + 4]);
            float a[TM] = {a0.x, a0.y, a0.z, a0.w, a1.x, a1.y, a1.z, a1.w};
            float b[TN] = {b0.x, b0.y, b0.z, b0.w, b1.x, b1.y, b1.z, b1.w};
#pragma unroll
            for (int i = 0; i < TM; i++)
#pragma unroll
                for (int j = 0; j < TN; j++) acc[i][j] += a[i] * b[j];
        }
        __syncthreads();
    }
#pragma unroll
    for (int i = 0; i < TM; i++) {
        int r = bm + ty * TM + i;
        if (r < M) {
            float4 o0 = make_float4(acc[i][0], acc[i][1], acc[i][2], acc[i][3]);
            float4 o1 = make_float4(acc[i][4], acc[i][5], acc[i][6], acc[i][7]);
            *reinterpret_cast<float4*>(&C[(size_t)r * N + bn + tx * TN]) = o0;
            *reinterpret_cast<float4*>(&C[(size_t)r * N + bn + tx * TN + 4]) = o1;
        }
    }
}

// ---------------- edge logit + fused segment-max ----------------
// warp-per-edge; 8 warps/block, 8 edges per warp.
template <int H, int C, bool EA>
__global__ void edge_logit_kernel(const float* __restrict__ xl, const float* __restrict__ xr,
                                  const float* __restrict__ ea, const float* __restrict__ We,
                                  const float* __restrict__ att,
                                  const int* __restrict__ src, const int* __restrict__ dst,
                                  float* __restrict__ logit, unsigned* __restrict__ mx, int E) {
    constexpr int HC = H * C;
    __shared__ float s_att[HC];
    __shared__ float s_We[EA ? 8 * HC : 4];
    for (int i = threadIdx.x; i < HC; i += blockDim.x) s_att[i] = att[i];
    if (EA)
        for (int i = threadIdx.x; i < 8 * HC; i += blockDim.x) s_We[i] = We[i];
    __syncthreads();

    const int warp = threadIdx.x >> 5, lane = threadIdx.x & 31;
    const int base = (blockIdx.x * 8 + warp) * 8;
    for (int i = 0; i < 8; i++) {
        const int e = base + i;
        if (e >= E) return;
        const int s = src[e], d = dst[e];
        float ear[8];
        if (EA) {
#pragma unroll
            for (int k = 0; k < 8; k++) ear[k] = __ldg(&ea[(size_t)e * 8 + k]);
        }
        const float* xls = xl + (size_t)s * HC;
        const float* xrd = xr + (size_t)d * HC;
#pragma unroll
        for (int h = 0; h < H; h++) {
            float acc = 0.f;
            for (int c0 = lane * 4; c0 < C; c0 += 128) {
                const int idx = h * C + c0;
                float4 a = *reinterpret_cast<const float4*>(xls + idx);
                float4 b = *reinterpret_cast<const float4*>(xrd + idx);
                float vx = a.x + b.x, vy = a.y + b.y, vz = a.z + b.z, vw = a.w + b.w;
                if (EA) {
#pragma unroll
                    for (int k = 0; k < 8; k++) {
                        float4 w = *reinterpret_cast<const float4*>(&s_We[k * HC + idx]);
                        vx += ear[k] * w.x; vy += ear[k] * w.y;
                        vz += ear[k] * w.z; vw += ear[k] * w.w;
                    }
                }
                vx = (vx >= 0.f) ? vx : 0.2f * vx;
                vy = (vy >= 0.f) ? vy : 0.2f * vy;
                vz = (vz >= 0.f) ? vz : 0.2f * vz;
                vw = (vw >= 0.f) ? vw : 0.2f * vw;
                float4 t = *reinterpret_cast<const float4*>(&s_att[idx]);
                acc += t.x * vx + t.y * vy + t.z * vz + t.w * vw;
            }
#pragma unroll
            for (int o = 16; o > 0; o >>= 1) acc += __shfl_xor_sync(0xffffffffu, acc, o);
            if (lane == 0) {
                logit[(size_t)e * H + h] = acc;
                atomicMax(&mx[d * H + h], enc(acc));
            }
        }
    }
}

// ---------------- exp(logit - max) + segment-sum denominator ----------------
template <int H>
__global__ void edge_exp_kernel(float* __restrict__ logit, const unsigned* __restrict__ mx,
                                float* __restrict__ den, const int* __restrict__ dst, int E) {
    int i = blockIdx.x * blockDim.x + threadIdx.x;
    if (i >= E * H) return;
    int e = i / H, h = i - e * H;
    int d = dst[e];
    float m = dec(mx[d * H + h]);
    float ex = __expf(logit[i] - m);
    logit[i] = ex;
    atomicAdd(&den[d * H + h], ex);
}

// ---------------- alpha-weighted aggregation (vector scatter-add) ----------------
template <int H, int C>
__global__ void edge_aggr_kernel(const float* __restrict__ xl, const float* __restrict__ ex,
                                 const float* __restrict__ den,
                                 const int* __restrict__ src, const int* __restrict__ dst,
                                 float* __restrict__ out, int E) {
    constexpr int HC = H * C;
    const int warp = threadIdx.x >> 5, lane = threadIdx.x & 31;
    const int e = blockIdx.x * 8 + warp;
    if (e >= E) return;
    const int s = src[e], d = dst[e];
    const float* xls = xl + (size_t)s * HC;
    float* outd = out + (size_t)d * HC;
#pragma unroll
    for (int h = 0; h < H; h++) {
        float alpha = ex[(size_t)e * H + h] / (den[d * H + h] + 1e-16f);
        for (int c0 = lane * 4; c0 < C; c0 += 128) {
            float4 v = *reinterpret_cast<const float4*>(xls + h * C + c0);
            v.x *= alpha; v.y *= alpha; v.z *= alpha; v.w *= alpha;
            asm volatile("red.global.add.v4.f32 [%0], {%1, %2, %3, %4};"
                         :: "l"(outd + h * C + c0), "f"(v.x), "f"(v.y), "f"(v.z), "f"(v.w)
                         : "memory");
        }
    }
}

// ---------------- small helpers ----------------
__global__ void fill_softmax_state_kernel(unsigned* mx, float* den, int n) {
    int i = blockIdx.x * blockDim.x + threadIdx.x;
    if (i < n) { mx[i] = 0u; den[i] = 0.f; }
}
__global__ void init_bias_kernel(float* __restrict__ out, const float* __restrict__ b, int n, int D) {
    int i = blockIdx.x * blockDim.x + threadIdx.x;
    if (i < n) out[i] = b[i % D];
}
__global__ void last_idx_kernel(const int* __restrict__ n_nodes, int* __restrict__ last, int G) {
    if (threadIdx.x == 0 && blockIdx.x == 0) {
        int s = 0;
        for (int i = 0; i < G; i++) { s += n_nodes[i]; last[i] = s - 1; }
    }
}

// ---------------- final MLP head ----------------
__global__ void fc_kernel(const float* __restrict__ h, const int* __restrict__ last,
                          const float* __restrict__ W1, const float* __restrict__ b1,
                          const float* __restrict__ W2, const float* __restrict__ b2,
                          float* __restrict__ out) {
    __shared__ float row[384];
    __shared__ float red[64];
    const int g = blockIdx.x, t = threadIdx.x;   // 64 threads
    const int node = last[g];
    for (int i = t; i < 384; i += 64) row[i] = h[(size_t)node * 384 + i];
    __syncthreads();
    float acc = b1[t];
    for (int k = 0; k < 384; k++) acc += row[k] * W1[k * 64 + t];
    acc = fmaxf(acc, 0.f);
    red[t] = acc * W2[t];
    __syncthreads();
    if (t < 32) {
        float p = red[t] + red[t + 32];
#pragma unroll
        for (int o = 16; o > 0; o >>= 1) p += __shfl_xor_sync(0xffffffffu, p, o);
        if (t == 0) out[g] = p + b2[0];
    }
}

// ---------------- launch ----------------
extern "C" void kernel_launch(void* const* d_in, const int* in_sizes, int n_in,
                              void* d_out, int out_size) {
    const float* x       = (const float*)d_in[0];
    const float* ea      = (const float*)d_in[1];
    const float* Wl1     = (const float*)d_in[2];
    const float* Wr1     = (const float*)d_in[3];
    const float* We1     = (const float*)d_in[4];
    const float* att1    = (const float*)d_in[5];
    const float* b1      = (const float*)d_in[6];
    const float* Wl2     = (const float*)d_in[7];
    const float* Wr2     = (const float*)d_in[8];
    const float* We2     = (const float*)d_in[9];
    const float* att2    = (const float*)d_in[10];
    const float* b2      = (const float*)d_in[11];
    const float* Wlp     = (const float*)d_in[12];
    const float* Wrp     = (const float*)d_in[13];
    const float* attp    = (const float*)d_in[14];
    const float* bp      = (const float*)d_in[15];
    const float* Wfc1    = (const float*)d_in[16];
    const float* bfc1    = (const float*)d_in[17];
    const float* Wfc2    = (const float*)d_in[18];
    const float* bfc2    = (const float*)d_in[19];
    const int*   ei      = (const int*)d_in[20];
    const int*   eim     = (const int*)d_in[21];
    const int*   n_nodes = (const int*)d_in[22];

    const int N = N_NODES, E = N_EDGES;
    const int* src  = ei;
    const int* dst  = ei + E;
    const int* srcm = eim;
    const int* dstm = eim + E;

    float *bufA, *bufB, *bufC, *bufD, *logit, *den;
    unsigned* mx;
    int* last;
    cudaGetSymbolAddress((void**)&bufA, g_bufA);
    cudaGetSymbolAddress((void**)&bufB, g_bufB);
    cudaGetSymbolAddress((void**)&bufC, g_bufC);
    cudaGetSymbolAddress((void**)&bufD, g_bufD);
    cudaGetSymbolAddress((void**)&logit, g_logit);
    cudaGetSymbolAddress((void**)&mx, g_mx);
    cudaGetSymbolAddress((void**)&den, g_den);
    cudaGetSymbolAddress((void**)&last, g_last);

    const int MB = (N + 127) / 128;   // 157 row-blocks

    // ===== Layer 1: GATv2(64 -> 4x256), edge_attr =====
    gemm128_kernel<false><<<dim3(1024 / 128, MB), 256>>>(x, Wl1, bufA, N, 1024, 64);
    gemm128_kernel<false><<<dim3(1024 / 128, MB), 256>>>(x, Wr1, bufB, N, 1024, 64);
    fill_softmax_state_kernel<<<(N * 4 + 255) / 256, 256>>>(mx, den, N * 4);
    edge_logit_kernel<4, 256, true><<<(E + 63) / 64, 256>>>(bufA, bufB, ea, We1, att1,
                                                            src, dst, logit, mx, E);
    edge_exp_kernel<4><<<(E * 4 + 255) / 256, 256>>>(logit, mx, den, dst, E);
    init_bias_kernel<<<(N * 1024 + 255) / 256, 256>>>(bufC, b1, N * 1024, 1024);
    edge_aggr_kernel<4, 256><<<(E + 7) / 8, 256>>>(bufA, logit, den, src, dst, bufC, E);

    // ===== Layer 2: GATv2(1024 -> 4x64), edge_attr ===== (relu fused into A-load)
    gemm128_kernel<true><<<dim3(256 / 128, MB), 256>>>(bufC, Wl2, bufA, N, 256, 1024);
    gemm128_kernel<true><<<dim3(256 / 128, MB), 256>>>(bufC, Wr2, bufB, N, 256, 1024);
    fill_softmax_state_kernel<<<(N * 4 + 255) / 256, 256>>>(mx, den, N * 4);
    edge_logit_kernel<4, 64, true><<<(E + 63) / 64, 256>>>(bufA, bufB, ea, We2, att2,
                                                           src, dst, logit, mx, E);
    edge_exp_kernel<4><<<(E * 4 + 255) / 256, 256>>>(logit, mx, den, dst, E);
    init_bias_kernel<<<(N * 256 + 255) / 256, 256>>>(bufD, b2, N * 256, 256);
    edge_aggr_kernel<4, 64><<<(E + 7) / 8, 256>>>(bufA, logit, den, src, dst, bufD, E);

    // ===== Layer 3: GATv2(256 -> 6x64), no edge_attr, master edges ===== (relu fused)
    gemm128_kernel<true><<<dim3(384 / 128, MB), 256>>>(bufD, Wlp, bufA, N, 384, 256);
    gemm128_kernel<true><<<dim3(384 / 128, MB), 256>>>(bufD, Wrp, bufB, N, 384, 256);
    fill_softmax_state_kernel<<<(N * 6 + 255) / 256, 256>>>(mx, den, N * 6);
    edge_logit_kernel<6, 64, false><<<(E + 63) / 64, 256>>>(bufA, bufB, nullptr, nullptr, attp,
                                                            srcm, dstm, logit, mx, E);
    edge_exp_kernel<6><<<(E * 6 + 255) / 256, 256>>>(logit, mx, den, dstm, E);
    init_bias_kernel<<<(N * 384 + 255) / 256, 256>>>(bufC, bp, N * 384, 384);
    edge_aggr_kernel<6, 64><<<(E + 7) / 8, 256>>>(bufA, logit, den, srcm, dstm, bufC, E);

    // ===== readout + MLP head =====
    last_idx_kernel<<<1, 32>>>(n_nodes, last, N_GRAPHS);
    fc_kernel<<<N_GRAPHS, 64>>>(bufC, last, Wfc1, bfc1, Wfc2, bfc2, (float*)d_out);
}

// round 3
// speedup vs baseline: 1.4354x; 1.0645x over previous
#include <cuda_runtime.h>
#include <cstdint>
#include <math_constants.h>

#define N_NODES  20000
#define N_EDGES  160000
#define N_GRAPHS 100

// ---------------- scratch (device globals; no allocation allowed) ----------------
__device__ float g_bufA[N_NODES * 1024];
__device__ float g_bufB[N_NODES * 1024];
__device__ float g_bufC[N_NODES * 1024];
__device__ float g_bufD[N_NODES * 1024];
__device__ float g_logit[N_EDGES * 6];
__device__ int   g_deg[N_NODES];
__device__ int   g_work[N_NODES];
__device__ int   g_ptr[N_NODES + 1];     // CSR for edge_index (layers 1,2)
__device__ int   g_eid[N_EDGES];
__device__ int   g_esrc[N_EDGES];
__device__ int   g_ptr2[N_NODES + 1];    // CSR for edge_index_master (layer 3)
__device__ int   g_eid2[N_EDGES];
__device__ int   g_esrc2[N_EDGES];
__device__ int   g_last[N_GRAPHS];

// ---------------- CSR build ----------------
__global__ void zero_int_kernel(int* p, int n) {
    int i = blockIdx.x * blockDim.x + threadIdx.x;
    if (i < n) p[i] = 0;
}
__global__ void degree_kernel(const int* __restrict__ dst, int* __restrict__ deg, int E) {
    int i = blockIdx.x * blockDim.x + threadIdx.x;
    if (i < E) atomicAdd(&deg[dst[i]], 1);
}
// exclusive scan over n<=20480 ints, single block of 1024 threads
__global__ void scan_kernel(const int* __restrict__ deg, int* __restrict__ ptr,
                            int* __restrict__ work, int n) {
    __shared__ int sm[1024];
    const int tid = threadIdx.x;
    const int chunk = (n + 1023) >> 10;
    const int start = tid * chunk;
    const int end = min(start + chunk, n);
    int s = 0;
    for (int i = start; i < end; i++) s += deg[i];
    sm[tid] = s;
    __syncthreads();
    for (int off = 1; off < 1024; off <<= 1) {
        int v = (tid >= off) ? sm[tid - off] : 0;
        __syncthreads();
        sm[tid] += v;
        __syncthreads();
    }
    int excl = (tid == 0) ? 0 : sm[tid - 1];
    for (int i = start; i < end; i++) {
        ptr[i] = excl;
        work[i] = excl;
        excl += deg[i];
    }
    if (tid == 0) ptr[n] = sm[1023];
}
__global__ void scatter_kernel(const int* __restrict__ src, const int* __restrict__ dst,
                               int* __restrict__ work, int* __restrict__ eid,
                               int* __restrict__ esrc, int E) {
    int e = blockIdx.x * blockDim.x + threadIdx.x;
    if (e < E) {
        int p = atomicAdd(&work[dst[e]], 1);
        eid[p] = e;
        esrc[p] = src[e];
    }
}

// ---------------- double-buffered fp32 GEMM: C = A[M,K] @ B[K,N] ----------------
__global__ void __launch_bounds__(256)
gemm128_db_kernel(const float* __restrict__ A, const float* __restrict__ B,
                  float* __restrict__ C, int M, int N, int K) {
    constexpr int BM = 128, BN = 128, BK = 16, TM = 8, TN = 8;
    __shared__ float As[2][BK][BM];
    __shared__ float Bs[2][BK][BN];
    const int bm = blockIdx.y * BM;
    const int bn = blockIdx.x * BN;
    const int tid = threadIdx.x;
    const int tx = tid & 15;
    const int ty = tid >> 4;

    // per-thread load slots: v and v+256 (512 float4s each tile)
    const int arow0 = tid >> 2,          akq0 = (tid & 3) * 4;
    const int arow1 = (tid + 256) >> 2,  akq1 = ((tid + 256) & 3) * 4;
    const int brow0 = tid >> 5,          bcq0 = (tid & 31) * 4;
    const int brow1 = (tid + 256) >> 5,  bcq1 = ((tid + 256) & 31) * 4;

    float acc[TM][TN];
#pragma unroll
    for (int i = 0; i < TM; i++)
#pragma unroll
        for (int j = 0; j < TN; j++) acc[i][j] = 0.f;

    auto ldA = [&](int k0, int row, int kq) -> float4 {
        float4 t = make_float4(0.f, 0.f, 0.f, 0.f);
        if (bm + row < M)
            t = *reinterpret_cast<const float4*>(&A[(size_t)(bm + row) * K + k0 + kq]);
        return t;
    };
    auto ldB = [&](int k0, int row, int cq) -> float4 {
        return *reinterpret_cast<const float4*>(&B[(size_t)(k0 + row) * N + bn + cq]);
    };
    auto stA = [&](int buf, int row, int kq, float4 t) {
        As[buf][kq + 0][row] = t.x;
        As[buf][kq + 1][row] = t.y;
        As[buf][kq + 2][row] = t.z;
        As[buf][kq + 3][row] = t.w;
    };

    // prologue: tile 0 -> buffer 0
    stA(0, arow0, akq0, ldA(0, arow0, akq0));
    stA(0, arow1, akq1, ldA(0, arow1, akq1));
    *reinterpret_cast<float4*>(&Bs[0][brow0][bcq0]) = ldB(0, brow0, bcq0);
    *reinterpret_cast<float4*>(&Bs[0][brow1][bcq1]) = ldB(0, brow1, bcq1);
    __syncthreads();

    int p = 0;
    for (int k0 = 0; k0 < K; k0 += BK) {
        const bool has_next = (k0 + BK) < K;
        float4 pa0, pa1, pb0, pb1;
        if (has_next) {
            pa0 = ldA(k0 + BK, arow0, akq0);
            pa1 = ldA(k0 + BK, arow1, akq1);
            pb0 = ldB(k0 + BK, brow0, bcq0);
            pb1 = ldB(k0 + BK, brow1, bcq1);
        }
#pragma unroll
        for (int kk = 0; kk < BK; kk++) {
            float4 a0 = *reinterpret_cast<const float4*>(&As[p][kk][ty * TM]);
            float4 a1 = *reinterpret_cast<const float4*>(&As[p][kk][ty * TM + 4]);
            float4 b0 = *reinterpret_cast<const float4*>(&Bs[p][kk][tx * TN]);
            float4 b1 = *reinterpret_cast<const float4*>(&Bs[p][kk][tx * TN + 4]);
            float a[TM] = {a0.x, a0.y, a0.z, a0.w, a1.x, a1.y, a1.z, a1.w};
            float b[TN] = {b0.x, b0.y, b0.z, b0.w, b1.x, b1.y, b1.z, b1.w};
#pragma unroll
            for (int i = 0; i < TM; i++)
#pragma unroll
                for (int j = 0; j < TN; j++) acc[i][j] += a[i] * b[j];
        }
        if (has_next) {
            stA(p ^ 1, arow0, akq0, pa0);
            stA(p ^ 1, arow1, akq1, pa1);
            *reinterpret_cast<float4*>(&Bs[p ^ 1][brow0][bcq0]) = pb0;
            *reinterpret_cast<float4*>(&Bs[p ^ 1][brow1][bcq1]) = pb1;
        }
        __syncthreads();
        p ^= 1;
    }
#pragma unroll
    for (int i = 0; i < TM; i++) {
        int r = bm + ty * TM + i;
        if (r < M) {
            float4 o0 = make_float4(acc[i][0], acc[i][1], acc[i][2], acc[i][3]);
            float4 o1 = make_float4(acc[i][4], acc[i][5], acc[i][6], acc[i][7]);
            *reinterpret_cast<float4*>(&C[(size_t)r * N + bn + tx * TN]) = o0;
            *reinterpret_cast<float4*>(&C[(size_t)r * N + bn + tx * TN + 4]) = o1;
        }
    }
}

// ---------------- fused per-node attention (warp per dst node, CSR) ----------------
// pass1: logits + online softmax (regs). pass2: alpha-weighted aggregation.
// out[d] = sum_e alpha * xl[src_e] + bias, optional relu. No atomics anywhere.
template <int H, int C, bool EA, bool RELU>
__global__ void __launch_bounds__(256)
node_attn_kernel(const float* __restrict__ xl, const float* __restrict__ xr,
                 const float* __restrict__ ea, const float* __restrict__ We,
                 const float* __restrict__ att, const float* __restrict__ bias,
                 const int* __restrict__ ptr, const int* __restrict__ eid,
                 const int* __restrict__ esrc,
                 float* __restrict__ logit_buf, float* __restrict__ out, int n) {
    constexpr int HC = H * C;
    constexpr int F4 = HC / 128;               // float4s per lane
    __shared__ float s_att[HC];
    __shared__ float s_We[EA ? 8 * HC : 4];
    for (int i = threadIdx.x; i < HC; i += blockDim.x) s_att[i] = att[i];
    if (EA)
        for (int i = threadIdx.x; i < 8 * HC; i += blockDim.x) s_We[i] = We[i];
    __syncthreads();

    const int warp = threadIdx.x >> 5, lane = threadIdx.x & 31;
    const int d = blockIdx.x * 8 + warp;
    if (d >= n) return;
    const int p0 = ptr[d], p1 = ptr[d + 1];

    int idxj[F4];
#pragma unroll
    for (int j = 0; j < F4; j++) idxj[j] = lane * 4 + j * 128;

    // cache xr[d] row in registers (read once per node, not per edge)
    float4 xrv[F4];
#pragma unroll
    for (int j = 0; j < F4; j++)
        xrv[j] = *reinterpret_cast<const float4*>(xr + (size_t)d * HC + idxj[j]);

    float mxj[F4], denj[F4];
#pragma unroll
    for (int j = 0; j < F4; j++) { mxj[j] = -CUDART_INF_F; denj[j] = 0.f; }

    // ---- pass 1: logits + online softmax ----
    for (int p = p0; p < p1; p++) {
        const int s = esrc[p];
        const float* xs = xl + (size_t)s * HC;
        float ear[8];
        if (EA) {
            const float* er = ea + (size_t)eid[p] * 8;
#pragma unroll
            for (int k = 0; k < 8; k++) ear[k] = __ldg(er + k);
        }
        float dotj[F4];
#pragma unroll
        for (int j = 0; j < F4; j++) {
            float4 a = *reinterpret_cast<const float4*>(xs + idxj[j]);
            float vx = a.x + xrv[j].x, vy = a.y + xrv[j].y;
            float vz = a.z + xrv[j].z, vw = a.w + xrv[j].w;
            if (EA) {
#pragma unroll
                for (int k = 0; k < 8; k++) {
                    float4 w = *reinterpret_cast<const float4*>(&s_We[k * HC + idxj[j]]);
                    vx += ear[k] * w.x; vy += ear[k] * w.y;
                    vz += ear[k] * w.z; vw += ear[k] * w.w;
                }
            }
            vx = (vx >= 0.f) ? vx : 0.2f * vx;
            vy = (vy >= 0.f) ? vy : 0.2f * vy;
            vz = (vz >= 0.f) ? vz : 0.2f * vz;
            vw = (vw >= 0.f) ? vw : 0.2f * vw;
            float4 t = *reinterpret_cast<const float4*>(&s_att[idxj[j]]);
            dotj[j] = t.x * vx + t.y * vy + t.z * vz + t.w * vw;
        }
        float tj[F4];
        if constexpr (C >= 128) {
            constexpr int JPH = C / 128;       // j-slots per head
#pragma unroll
            for (int h = 0; h < H; h++) {
                float sacc = 0.f;
#pragma unroll
                for (int m = 0; m < JPH; m++) sacc += dotj[h * JPH + m];
#pragma unroll
                for (int o = 16; o > 0; o >>= 1) sacc += __shfl_xor_sync(0xffffffffu, sacc, o);
#pragma unroll
                for (int m = 0; m < JPH; m++) tj[h * JPH + m] = sacc;
            }
        } else {                               // C == 64: head spans 16 lanes
#pragma unroll
            for (int j = 0; j < F4; j++) {
                float sacc = dotj[j];
#pragma unroll
                for (int o = 8; o > 0; o >>= 1) sacc += __shfl_xor_sync(0xffffffffu, sacc, o);
                tj[j] = sacc;
            }
        }
#pragma unroll
        for (int j = 0; j < F4; j++) {
            if ((idxj[j] & (C - 1)) == 0)
                logit_buf[(size_t)p * H + (idxj[j] / C)] = tj[j];
            float mn = fmaxf(mxj[j], tj[j]);
            denj[j] = denj[j] * __expf(mxj[j] - mn) + __expf(tj[j] - mn);
            mxj[j] = mn;
        }
    }
    __threadfence_block();
    __syncwarp();

    // ---- pass 2: alpha-weighted aggregation ----
    float4 acc[F4];
#pragma unroll
    for (int j = 0; j < F4; j++) acc[j] = make_float4(0.f, 0.f, 0.f, 0.f);

    for (int p = p0; p < p1; p++) {
        const int s = esrc[p];
        const float* xs = xl + (size_t)s * HC;
#pragma unroll
        for (int j = 0; j < F4; j++) {
            float lg = logit_buf[(size_t)p * H + (idxj[j] / C)];
            float alpha = __expf(lg - mxj[j]) / (denj[j] + 1e-16f);
            float4 a = *reinterpret_cast<const float4*>(xs + idxj[j]);
            acc[j].x += alpha * a.x; acc[j].y += alpha * a.y;
            acc[j].z += alpha * a.z; acc[j].w += alpha * a.w;
        }
    }
#pragma unroll
    for (int j = 0; j < F4; j++) {
        float4 b = *reinterpret_cast<const float4*>(bias + idxj[j]);
        float4 o = make_float4(acc[j].x + b.x, acc[j].y + b.y,
                               acc[j].z + b.z, acc[j].w + b.w);
        if (RELU) {
            o.x = fmaxf(o.x, 0.f); o.y = fmaxf(o.y, 0.f);
            o.z = fmaxf(o.z, 0.f); o.w = fmaxf(o.w, 0.f);
        }
        *reinterpret_cast<float4*>(out + (size_t)d * HC + idxj[j]) = o;
    }
}

// ---------------- readout ----------------
__global__ void last_idx_kernel(const int* __restrict__ n_nodes, int* __restrict__ last, int G) {
    if (threadIdx.x == 0 && blockIdx.x == 0) {
        int s = 0;
        for (int i = 0; i < G; i++) { s += n_nodes[i]; last[i] = s - 1; }
    }
}
__global__ void fc_kernel(const float* __restrict__ h, const int* __restrict__ last,
                          const float* __restrict__ W1, const float* __restrict__ b1,
                          const float* __restrict__ W2, const float* __restrict__ b2,
                          float* __restrict__ out) {
    __shared__ float row[384];
    __shared__ float red[64];
    const int g = blockIdx.x, t = threadIdx.x;   // 64 threads
    const int node = last[g];
    for (int i = t; i < 384; i += 64) row[i] = h[(size_t)node * 384 + i];
    __syncthreads();
    float acc = b1[t];
    for (int k = 0; k < 384; k++) acc += row[k] * W1[k * 64 + t];
    acc = fmaxf(acc, 0.f);
    red[t] = acc * W2[t];
    __syncthreads();
    if (t < 32) {
        float p = red[t] + red[t + 32];
#pragma unroll
        for (int o = 16; o > 0; o >>= 1) p += __shfl_xor_sync(0xffffffffu, p, o);
        if (t == 0) out[g] = p + b2[0];
    }
}

// ---------------- launch ----------------
extern "C" void kernel_launch(void* const* d_in, const int* in_sizes, int n_in,
                              void* d_out, int out_size) {
    const float* x       = (const float*)d_in[0];
    const float* ea      = (const float*)d_in[1];
    const float* Wl1     = (const float*)d_in[2];
    const float* Wr1     = (const float*)d_in[3];
    const float* We1     = (const float*)d_in[4];
    const float* att1    = (const float*)d_in[5];
    const float* b1      = (const float*)d_in[6];
    const float* Wl2     = (const float*)d_in[7];
    const float* Wr2     = (const float*)d_in[8];
    const float* We2     = (const float*)d_in[9];
    const float* att2    = (const float*)d_in[10];
    const float* b2      = (const float*)d_in[11];
    const float* Wlp     = (const float*)d_in[12];
    const float* Wrp     = (const float*)d_in[13];
    const float* attp    = (const float*)d_in[14];
    const float* bp      = (const float*)d_in[15];
    const float* Wfc1    = (const float*)d_in[16];
    const float* bfc1    = (const float*)d_in[17];
    const float* Wfc2    = (const float*)d_in[18];
    const float* bfc2    = (const float*)d_in[19];
    const int*   ei      = (const int*)d_in[20];
    const int*   eim     = (const int*)d_in[21];
    const int*   n_nodes = (const int*)d_in[22];

    const int N = N_NODES, E = N_EDGES;
    const int* src  = ei;
    const int* dst  = ei + E;
    const int* srcm = eim;
    const int* dstm = eim + E;

    float *bufA, *bufB, *bufC, *bufD, *logit;
    int *deg, *work, *ptr, *eid, *esrc, *ptr2, *eid2, *esrc2, *last;
    cudaGetSymbolAddress((void**)&bufA, g_bufA);
    cudaGetSymbolAddress((void**)&bufB, g_bufB);
    cudaGetSymbolAddress((void**)&bufC, g_bufC);
    cudaGetSymbolAddress((void**)&bufD, g_bufD);
    cudaGetSymbolAddress((void**)&logit, g_logit);
    cudaGetSymbolAddress((void**)&deg, g_deg);
    cudaGetSymbolAddress((void**)&work, g_work);
    cudaGetSymbolAddress((void**)&ptr, g_ptr);
    cudaGetSymbolAddress((void**)&eid, g_eid);
    cudaGetSymbolAddress((void**)&esrc, g_esrc);
    cudaGetSymbolAddress((void**)&ptr2, g_ptr2);
    cudaGetSymbolAddress((void**)&eid2, g_eid2);
    cudaGetSymbolAddress((void**)&esrc2, g_esrc2);
    cudaGetSymbolAddress((void**)&last, g_last);

    const int MB = (N + 127) / 128;
    const int EB = (E + 255) / 256;
    const int NB = (N + 255) / 256;

    // ===== CSR builds =====
    zero_int_kernel<<<NB, 256>>>(deg, N);
    degree_kernel<<<EB, 256>>>(dst, deg, E);
    scan_kernel<<<1, 1024>>>(deg, ptr, work, N);
    scatter_kernel<<<EB, 256>>>(src, dst, work, eid, esrc, E);

    zero_int_kernel<<<NB, 256>>>(deg, N);
    degree_kernel<<<EB, 256>>>(dstm, deg, E);
    scan_kernel<<<1, 1024>>>(deg, ptr2, work, N);
    scatter_kernel<<<EB, 256>>>(srcm, dstm, work, eid2, esrc2, E);

    // ===== Layer 1: GATv2(64 -> 4x256), edge_attr, relu fused =====
    gemm128_db_kernel<<<dim3(1024 / 128, MB), 256>>>(x, Wl1, bufA, N, 1024, 64);
    gemm128_db_kernel<<<dim3(1024 / 128, MB), 256>>>(x, Wr1, bufB, N, 1024, 64);
    node_attn_kernel<4, 256, true, true><<<(N + 7) / 8, 256>>>(
        bufA, bufB, ea, We1, att1, b1, ptr, eid, esrc, logit, bufC, N);

    // ===== Layer 2: GATv2(1024 -> 4x64), edge_attr, relu fused =====
    gemm128_db_kernel<<<dim3(256 / 128, MB), 256>>>(bufC, Wl2, bufA, N, 256, 1024);
    gemm128_db_kernel<<<dim3(256 / 128, MB), 256>>>(bufC, Wr2, bufB, N, 256, 1024);
    node_attn_kernel<4, 64, true, true><<<(N + 7) / 8, 256>>>(
        bufA, bufB, ea, We2, att2, b2, ptr, eid, esrc, logit, bufD, N);

    // ===== Layer 3: GATv2(256 -> 6x64), no edge_attr, master edges =====
    gemm128_db_kernel<<<dim3(384 / 128, MB), 256>>>(bufD, Wlp, bufA, N, 384, 256);
    gemm128_db_kernel<<<dim3(384 / 128, MB), 256>>>(bufD, Wrp, bufB, N, 384, 256);
    node_attn_kernel<6, 64, false, false><<<(N + 7) / 8, 256>>>(
        bufA, bufB, nullptr, nullptr, attp, bp, ptr2, eid2, esrc2, logit, bufC, N);

    // ===== readout + MLP head =====
    last_idx_kernel<<<1, 32>>>(n_nodes, last, N_GRAPHS);
    fc_kernel<<<N_GRAPHS, 64>>>(bufC, last, Wfc1, bfc1, Wfc2, bfc2, (float*)d_out);
}

// round 4
// speedup vs baseline: 1.4922x; 1.0396x over previous
#include <cuda_runtime.h>
#include <cstdint>
#include <math_constants.h>

#define N_NODES  20000
#define N_EDGES  160000
#define N_GRAPHS 100

// ---------------- scratch (device globals; no allocation allowed) ----------------
__device__ float g_bufA[N_NODES * 1024];
__device__ float g_bufB[N_NODES * 1024];
__device__ float g_bufC[N_NODES * 1024];
__device__ float g_bufD[N_NODES * 1024];
__device__ float g_logit[N_EDGES * 6];
__device__ int   g_deg[N_NODES];
__device__ int   g_work[N_NODES];
__device__ int   g_ptr[N_NODES + 1];     // CSR for edge_index (layers 1,2)
__device__ int   g_eid[N_EDGES];
__device__ int   g_esrc[N_EDGES];
__device__ int   g_ptr2[N_NODES + 1];    // CSR for edge_index_master (layer 3)
__device__ int   g_eid2[N_EDGES];
__device__ int   g_esrc2[N_EDGES];
__device__ int   g_last[N_GRAPHS];

// ---------------- CSR build ----------------
__global__ void zero_int_kernel(int* p, int n) {
    int i = blockIdx.x * blockDim.x + threadIdx.x;
    if (i < n) p[i] = 0;
}
__global__ void degree_kernel(const int* __restrict__ dst, int* __restrict__ deg, int E) {
    int i = blockIdx.x * blockDim.x + threadIdx.x;
    if (i < E) atomicAdd(&deg[dst[i]], 1);
}
// exclusive scan over n<=20480 ints, single block of 1024 threads
__global__ void scan_kernel(const int* __restrict__ deg, int* __restrict__ ptr,
                            int* __restrict__ work, int n) {
    __shared__ int sm[1024];
    const int tid = threadIdx.x;
    const int chunk = (n + 1023) >> 10;
    const int start = tid * chunk;
    const int end = min(start + chunk, n);
    int s = 0;
    for (int i = start; i < end; i++) s += deg[i];
    sm[tid] = s;
    __syncthreads();
    for (int off = 1; off < 1024; off <<= 1) {
        int v = (tid >= off) ? sm[tid - off] : 0;
        __syncthreads();
        sm[tid] += v;
        __syncthreads();
    }
    int excl = (tid == 0) ? 0 : sm[tid - 1];
    for (int i = start; i < end; i++) {
        ptr[i] = excl;
        work[i] = excl;
        excl += deg[i];
    }
    if (tid == 0) ptr[n] = sm[1023];
}
__global__ void scatter_kernel(const int* __restrict__ src, const int* __restrict__ dst,
                               int* __restrict__ work, int* __restrict__ eid,
                               int* __restrict__ esrc, int E) {
    int e = blockIdx.x * blockDim.x + threadIdx.x;
    if (e < E) {
        int p = atomicAdd(&work[dst[e]], 1);
        eid[p] = e;
        esrc[p] = src[e];
    }
}

// ---------------- f32x2 packed double-buffered GEMM ----------------
// C{z} = A[M,K] @ B{z}[K,N], z=blockIdx.z selects (B0,C0) or (B1,C1).
// Accumulators are packed f32x2 (u64) column pairs; fma.rn.f32x2 = 2 fp32 FMA/lane.
__global__ void __launch_bounds__(256)
gemm128_x2_kernel(const float* __restrict__ A,
                  const float* __restrict__ B0, const float* __restrict__ B1,
                  float* __restrict__ C0, float* __restrict__ C1,
                  int M, int N, int K) {
    constexpr int BM = 128, BN = 128, BK = 16, TM = 8;
    __shared__ __align__(16) float As[2][BK][BM];
    __shared__ __align__(16) float Bs[2][BK][BN];
    const float* B = blockIdx.z ? B1 : B0;
    float* C = blockIdx.z ? C1 : C0;
    const int bm = blockIdx.y * BM;
    const int bn = blockIdx.x * BN;
    const int tid = threadIdx.x;
    const int tx = tid & 15;
    const int ty = tid >> 4;

    const int arow0 = tid >> 2,          akq0 = (tid & 3) * 4;
    const int arow1 = (tid + 256) >> 2,  akq1 = ((tid + 256) & 3) * 4;
    const int brow0 = tid >> 5,          bcq0 = (tid & 31) * 4;
    const int brow1 = (tid + 256) >> 5,  bcq1 = ((tid + 256) & 31) * 4;

    unsigned long long acc[TM][4];
#pragma unroll
    for (int i = 0; i < TM; i++)
#pragma unroll
        for (int j = 0; j < 4; j++) acc[i][j] = 0ull;

    auto ldA = [&](int k0, int row, int kq) -> float4 {
        float4 t = make_float4(0.f, 0.f, 0.f, 0.f);
        if (bm + row < M)
            t = *reinterpret_cast<const float4*>(&A[(size_t)(bm + row) * K + k0 + kq]);
        return t;
    };
    auto ldB = [&](int k0, int row, int cq) -> float4 {
        return *reinterpret_cast<const float4*>(&B[(size_t)(k0 + row) * N + bn + cq]);
    };
    auto stA = [&](int buf, int row, int kq, float4 t) {
        As[buf][kq + 0][row] = t.x;
        As[buf][kq + 1][row] = t.y;
        As[buf][kq + 2][row] = t.z;
        As[buf][kq + 3][row] = t.w;
    };

    stA(0, arow0, akq0, ldA(0, arow0, akq0));
    stA(0, arow1, akq1, ldA(0, arow1, akq1));
    *reinterpret_cast<float4*>(&Bs[0][brow0][bcq0]) = ldB(0, brow0, bcq0);
    *reinterpret_cast<float4*>(&Bs[0][brow1][bcq1]) = ldB(0, brow1, bcq1);
    __syncthreads();

    int p = 0;
    for (int k0 = 0; k0 < K; k0 += BK) {
        const bool has_next = (k0 + BK) < K;
        float4 pa0, pa1, pb0, pb1;
        if (has_next) {
            pa0 = ldA(k0 + BK, arow0, akq0);
            pa1 = ldA(k0 + BK, arow1, akq1);
            pb0 = ldB(k0 + BK, brow0, bcq0);
            pb1 = ldB(k0 + BK, brow1, bcq1);
        }
#pragma unroll
        for (int kk = 0; kk < BK; kk++) {
            float4 a0 = *reinterpret_cast<const float4*>(&As[p][kk][ty * TM]);
            float4 a1 = *reinterpret_cast<const float4*>(&As[p][kk][ty * TM + 4]);
            ulonglong2 bb0 = *reinterpret_cast<const ulonglong2*>(&Bs[p][kk][tx * 8]);
            ulonglong2 bb1 = *reinterpret_cast<const ulonglong2*>(&Bs[p][kk][tx * 8 + 4]);
            unsigned long long b[4] = {bb0.x, bb0.y, bb1.x, bb1.y};
            float a[TM] = {a0.x, a0.y, a0.z, a0.w, a1.x, a1.y, a1.z, a1.w};
#pragma unroll
            for (int i = 0; i < TM; i++) {
                unsigned long long a2;
                asm("mov.b64 %0, {%1, %1};" : "=l"(a2) : "f"(a[i]));
#pragma unroll
                for (int j = 0; j < 4; j++)
                    asm("fma.rn.f32x2 %0, %1, %2, %0;" : "+l"(acc[i][j]) : "l"(a2), "l"(b[j]));
            }
        }
        if (has_next) {
            stA(p ^ 1, arow0, akq0, pa0);
            stA(p ^ 1, arow1, akq1, pa1);
            *reinterpret_cast<float4*>(&Bs[p ^ 1][brow0][bcq0]) = pb0;
            *reinterpret_cast<float4*>(&Bs[p ^ 1][brow1][bcq1]) = pb1;
        }
        __syncthreads();
        p ^= 1;
    }
#pragma unroll
    for (int i = 0; i < TM; i++) {
        int r = bm + ty * TM + i;
        if (r < M) {
            // packed f32x2 pair layout == two consecutive floats (lane0 = low word)
            ulonglong2 o0 = make_ulonglong2(acc[i][0], acc[i][1]);
            ulonglong2 o1 = make_ulonglong2(acc[i][2], acc[i][3]);
            *reinterpret_cast<ulonglong2*>(&C[(size_t)r * N + bn + tx * 8]) = o0;
            *reinterpret_cast<ulonglong2*>(&C[(size_t)r * N + bn + tx * 8 + 4]) = o1;
        }
    }
}

// ---------------- fused per-node attention (warp per dst node, CSR) ----------------
template <int H, int C, bool EA, bool RELU>
__global__ void __launch_bounds__(256)
node_attn_kernel(const float* __restrict__ xl, const float* __restrict__ xr,
                 const float* __restrict__ ea, const float* __restrict__ We,
                 const float* __restrict__ att, const float* __restrict__ bias,
                 const int* __restrict__ ptr, const int* __restrict__ eid,
                 const int* __restrict__ esrc,
                 float* __restrict__ logit_buf, float* __restrict__ out, int n) {
    constexpr int HC = H * C;
    constexpr int F4 = HC / 128;               // float4s per lane
    __shared__ float s_att[HC];
    __shared__ float s_We[EA ? 8 * HC : 4];
    for (int i = threadIdx.x; i < HC; i += blockDim.x) s_att[i] = att[i];
    if (EA)
        for (int i = threadIdx.x; i < 8 * HC; i += blockDim.x) s_We[i] = We[i];
    __syncthreads();

    const int warp = threadIdx.x >> 5, lane = threadIdx.x & 31;
    const int d = blockIdx.x * 8 + warp;
    if (d >= n) return;
    const int p0 = ptr[d], p1 = ptr[d + 1];

    int idxj[F4];
#pragma unroll
    for (int j = 0; j < F4; j++) idxj[j] = lane * 4 + j * 128;

    float4 xrv[F4];
#pragma unroll
    for (int j = 0; j < F4; j++)
        xrv[j] = *reinterpret_cast<const float4*>(xr + (size_t)d * HC + idxj[j]);

    float mxj[F4], denj[F4];
#pragma unroll
    for (int j = 0; j < F4; j++) { mxj[j] = -CUDART_INF_F; denj[j] = 0.f; }

    // ---- pass 1: logits + online softmax ----
    for (int p = p0; p < p1; p++) {
        const int s = esrc[p];
        const float* xs = xl + (size_t)s * HC;
        float ear[8];
        if (EA) {
            const float* er = ea + (size_t)eid[p] * 8;
#pragma unroll
            for (int k = 0; k < 8; k++) ear[k] = __ldg(er + k);
        }
        float dotj[F4];
#pragma unroll
        for (int j = 0; j < F4; j++) {
            float4 a = *reinterpret_cast<const float4*>(xs + idxj[j]);
            float vx = a.x + xrv[j].x, vy = a.y + xrv[j].y;
            float vz = a.z + xrv[j].z, vw = a.w + xrv[j].w;
            if (EA) {
#pragma unroll
                for (int k = 0; k < 8; k++) {
                    float4 w = *reinterpret_cast<const float4*>(&s_We[k * HC + idxj[j]]);
                    vx += ear[k] * w.x; vy += ear[k] * w.y;
                    vz += ear[k] * w.z; vw += ear[k] * w.w;
                }
            }
            vx = (vx >= 0.f) ? vx : 0.2f * vx;
            vy = (vy >= 0.f) ? vy : 0.2f * vy;
            vz = (vz >= 0.f) ? vz : 0.2f * vz;
            vw = (vw >= 0.f) ? vw : 0.2f * vw;
            float4 t = *reinterpret_cast<const float4*>(&s_att[idxj[j]]);
            dotj[j] = t.x * vx + t.y * vy + t.z * vz + t.w * vw;
        }
        float tj[F4];
        if constexpr (C >= 128) {
            constexpr int JPH = C / 128;
#pragma unroll
            for (int h = 0; h < H; h++) {
                float sacc = 0.f;
#pragma unroll
                for (int m = 0; m < JPH; m++) sacc += dotj[h * JPH + m];
#pragma unroll
                for (int o = 16; o > 0; o >>= 1) sacc += __shfl_xor_sync(0xffffffffu, sacc, o);
#pragma unroll
                for (int m = 0; m < JPH; m++) tj[h * JPH + m] = sacc;
            }
        } else {                               // C == 64: head spans 16 lanes
#pragma unroll
            for (int j = 0; j < F4; j++) {
                float sacc = dotj[j];
#pragma unroll
                for (int o = 8; o > 0; o >>= 1) sacc += __shfl_xor_sync(0xffffffffu, sacc, o);
                tj[j] = sacc;
            }
        }
#pragma unroll
        for (int j = 0; j < F4; j++) {
            if ((idxj[j] & (C - 1)) == 0)
                logit_buf[(size_t)p * H + (idxj[j] / C)] = tj[j];
            float mn = fmaxf(mxj[j], tj[j]);
            denj[j] = denj[j] * __expf(mxj[j] - mn) + __expf(tj[j] - mn);
            mxj[j] = mn;
        }
    }
    __threadfence_block();
    __syncwarp();

    // ---- pass 2: alpha-weighted aggregation ----
    float4 acc[F4];
#pragma unroll
    for (int j = 0; j < F4; j++) acc[j] = make_float4(0.f, 0.f, 0.f, 0.f);

    for (int p = p0; p < p1; p++) {
        const int s = esrc[p];
        const float* xs = xl + (size_t)s * HC;
#pragma unroll
        for (int j = 0; j < F4; j++) {
            float lg = logit_buf[(size_t)p * H + (idxj[j] / C)];
            float alpha = __expf(lg - mxj[j]) / (denj[j] + 1e-16f);
            float4 a = *reinterpret_cast<const float4*>(xs + idxj[j]);
            acc[j].x += alpha * a.x; acc[j].y += alpha * a.y;
            acc[j].z += alpha * a.z; acc[j].w += alpha * a.w;
        }
    }
#pragma unroll
    for (int j = 0; j < F4; j++) {
        float4 b = *reinterpret_cast<const float4*>(bias + idxj[j]);
        float4 o = make_float4(acc[j].x + b.x, acc[j].y + b.y,
                               acc[j].z + b.z, acc[j].w + b.w);
        if (RELU) {
            o.x = fmaxf(o.x, 0.f); o.y = fmaxf(o.y, 0.f);
            o.z = fmaxf(o.z, 0.f); o.w = fmaxf(o.w, 0.f);
        }
        *reinterpret_cast<float4*>(out + (size_t)d * HC + idxj[j]) = o;
    }
}

// ---------------- readout ----------------
__global__ void last_idx_kernel(const int* __restrict__ n_nodes, int* __restrict__ last, int G) {
    if (threadIdx.x == 0 && blockIdx.x == 0) {
        int s = 0;
        for (int i = 0; i < G; i++) { s += n_nodes[i]; last[i] = s - 1; }
    }
}
__global__ void fc_kernel(const float* __restrict__ h, const int* __restrict__ last,
                          const float* __restrict__ W1, const float* __restrict__ b1,
                          const float* __restrict__ W2, const float* __restrict__ b2,
                          float* __restrict__ out) {
    __shared__ float row[384];
    __shared__ float red[64];
    const int g = blockIdx.x, t = threadIdx.x;   // 64 threads
    const int node = last[g];
    for (int i = t; i < 384; i += 64) row[i] = h[(size_t)node * 384 + i];
    __syncthreads();
    float acc = b1[t];
    for (int k = 0; k < 384; k++) acc += row[k] * W1[k * 64 + t];
    acc = fmaxf(acc, 0.f);
    red[t] = acc * W2[t];
    __syncthreads();
    if (t < 32) {
        float p = red[t] + red[t + 32];
#pragma unroll
        for (int o = 16; o > 0; o >>= 1) p += __shfl_xor_sync(0xffffffffu, p, o);
        if (t == 0) out[g] = p + b2[0];
    }
}

// ---------------- launch ----------------
extern "C" void kernel_launch(void* const* d_in, const int* in_sizes, int n_in,
                              void* d_out, int out_size) {
    const float* x       = (const float*)d_in[0];
    const float* ea      = (const float*)d_in[1];
    const float* Wl1     = (const float*)d_in[2];
    const float* Wr1     = (const float*)d_in[3];
    const float* We1     = (const float*)d_in[4];
    const float* att1    = (const float*)d_in[5];
    const float* b1      = (const float*)d_in[6];
    const float* Wl2     = (const float*)d_in[7];
    const float* Wr2     = (const float*)d_in[8];
    const float* We2     = (const float*)d_in[9];
    const float* att2    = (const float*)d_in[10];
    const float* b2      = (const float*)d_in[11];
    const float* Wlp     = (const float*)d_in[12];
    const float* Wrp     = (const float*)d_in[13];
    const float* attp    = (const float*)d_in[14];
    const float* bp      = (const float*)d_in[15];
    const float* Wfc1    = (const float*)d_in[16];
    const float* bfc1    = (const float*)d_in[17];
    const float* Wfc2    = (const float*)d_in[18];
    const float* bfc2    = (const float*)d_in[19];
    const int*   ei      = (const int*)d_in[20];
    const int*   eim     = (const int*)d_in[21];
    const int*   n_nodes = (const int*)d_in[22];

    const int N = N_NODES, E = N_EDGES;
    const int* src  = ei;
    const int* dst  = ei + E;
    const int* srcm = eim;
    const int* dstm = eim + E;

    float *bufA, *bufB, *bufC, *bufD, *logit;
    int *deg, *work, *ptr, *eid, *esrc, *ptr2, *eid2, *esrc2, *last;
    cudaGetSymbolAddress((void**)&bufA, g_bufA);
    cudaGetSymbolAddress((void**)&bufB, g_bufB);
    cudaGetSymbolAddress((void**)&bufC, g_bufC);
    cudaGetSymbolAddress((void**)&bufD, g_bufD);
    cudaGetSymbolAddress((void**)&logit, g_logit);
    cudaGetSymbolAddress((void**)&deg, g_deg);
    cudaGetSymbolAddress((void**)&work, g_work);
    cudaGetSymbolAddress((void**)&ptr, g_ptr);
    cudaGetSymbolAddress((void**)&eid, g_eid);
    cudaGetSymbolAddress((void**)&esrc, g_esrc);
    cudaGetSymbolAddress((void**)&ptr2, g_ptr2);
    cudaGetSymbolAddress((void**)&eid2, g_eid2);
    cudaGetSymbolAddress((void**)&esrc2, g_esrc2);
    cudaGetSymbolAddress((void**)&last, g_last);

    const int MB = (N + 127) / 128;
    const int EB = (E + 255) / 256;
    const int NB = (N + 255) / 256;

    // ===== CSR builds =====
    zero_int_kernel<<<NB, 256>>>(deg, N);
    degree_kernel<<<EB, 256>>>(dst, deg, E);
    scan_kernel<<<1, 1024>>>(deg, ptr, work, N);
    scatter_kernel<<<EB, 256>>>(src, dst, work, eid, esrc, E);

    zero_int_kernel<<<NB, 256>>>(deg, N);
    degree_kernel<<<EB, 256>>>(dstm, deg, E);
    scan_kernel<<<1, 1024>>>(deg, ptr2, work, N);
    scatter_kernel<<<EB, 256>>>(srcm, dstm, work, eid2, esrc2, E);

    // ===== Layer 1: GATv2(64 -> 4x256), edge_attr, relu fused =====
    gemm128_x2_kernel<<<dim3(1024 / 128, MB, 2), 256>>>(x, Wl1, Wr1, bufA, bufB, N, 1024, 64);
    node_attn_kernel<4, 256, true, true><<<(N + 7) / 8, 256>>>(
        bufA, bufB, ea, We1, att1, b1, ptr, eid, esrc, logit, bufC, N);

    // ===== Layer 2: GATv2(1024 -> 4x64), edge_attr, relu fused =====
    gemm128_x2_kernel<<<dim3(256 / 128, MB, 2), 256>>>(bufC, Wl2, Wr2, bufA, bufB, N, 256, 1024);
    node_attn_kernel<4, 64, true, true><<<(N + 7) / 8, 256>>>(
        bufA, bufB, ea, We2, att2, b2, ptr, eid, esrc, logit, bufD, N);

    // ===== Layer 3: GATv2(256 -> 6x64), no edge_attr, master edges =====
    gemm128_x2_kernel<<<dim3(384 / 128, MB, 2), 256>>>(bufD, Wlp, Wrp, bufA, bufB, N, 384, 256);
    node_attn_kernel<6, 64, false, false><<<(N + 7) / 8, 256>>>(
        bufA, bufB, nullptr, nullptr, attp, bp, ptr2, eid2, esrc2, logit, bufC, N);

    // ===== readout + MLP head =====
    last_idx_kernel<<<1, 32>>>(n_nodes, last, N_GRAPHS);
    fc_kernel<<<N_GRAPHS, 64>>>(bufC, last, Wfc1, bfc1, Wfc2, bfc2, (float*)d_out);
}